// round 15
// baseline (speedup 1.0000x reference)
#include <cuda_runtime.h>
#include <cstdint>
#include <cstddef>

#define D        1024
#define D4       256
#define NS       25
#define NWAY     5
#define NCHUNK   4
#define CW       256       // chunk width (floats)
#define CW4      64
#define CP       260       // chunk pitch (floats)
#define SROWS    28        // 25 rows padded to 28 (7 blocks of 4)
#define AUGC     32        // augmented matrix row stride
#define MAXB     1024
#define ROWS_PER_CTA 32    // logits: 8 warps x 4 rows

// global scratch
__device__ float g_Kp[MAXB * NCHUNK * NS * NS];  // partial K per chunk
__device__ float g_Wt[MAXB * NWAY * D];          // W^T class-major

// tile map: 28 upper-triangle pairs of 7 row-blocks (4 rows each)
__constant__ unsigned char t_bi[28] =
    {0,0,0,0,0,0,0, 1,1,1,1,1,1, 2,2,2,2,2, 3,3,3,3, 4,4,4, 5,5, 6};
__constant__ unsigned char t_bj[28] =
    {0,1,2,3,4,5,6, 1,2,3,4,5,6, 2,3,4,5,6, 3,4,5,6, 4,5,6, 5,6, 6};

// Multi-value butterfly: reduces 16 per-lane partials across the warp with
// 16 shuffles total. On exit, lane pair (2m, 2m+1) holds the full sum of
// acc[m] (m = (lane >> 1) & 15).
__device__ __forceinline__ void reduce16(float* a, int lane) {
    {
        const bool hi = (lane & 16) != 0;
        #pragma unroll
        for (int m = 0; m < 8; m++) {
            float mine  = hi ? a[m + 8] : a[m];
            float other = hi ? a[m]     : a[m + 8];
            a[m] = mine + __shfl_xor_sync(0xffffffffu, other, 16);
        }
    }
    {
        const bool hi = (lane & 8) != 0;
        #pragma unroll
        for (int m = 0; m < 4; m++) {
            float mine  = hi ? a[m + 4] : a[m];
            float other = hi ? a[m]     : a[m + 4];
            a[m] = mine + __shfl_xor_sync(0xffffffffu, other, 8);
        }
    }
    {
        const bool hi = (lane & 4) != 0;
        #pragma unroll
        for (int m = 0; m < 2; m++) {
            float mine  = hi ? a[m + 2] : a[m];
            float other = hi ? a[m]     : a[m + 2];
            a[m] = mine + __shfl_xor_sync(0xffffffffu, other, 4);
        }
    }
    {
        const bool hi = (lane & 2) != 0;
        float mine  = hi ? a[1] : a[0];
        float other = hi ? a[0] : a[1];
        a[0] = mine + __shfl_xor_sync(0xffffffffu, other, 2);
    }
    a[0] += __shfl_xor_sync(0xffffffffu, a[0], 1);
}

// ---------------------------------------------------------------------------
// Kernel 1: partial K = S_chunk S_chunk^T  -> g_Kp   grid(NCHUNK, Bslice)
//           (R10 measured-good, FROZEN; + batch offset)
// ---------------------------------------------------------------------------
struct SmK { float Sc[SROWS * CP]; };             // 29120 B

__global__ void __launch_bounds__(256, 5)
kpart_kernel(const float* __restrict__ support, float* __restrict__ kp, int b0)
{
    extern __shared__ __align__(16) char smem_raw[];
    SmK* sm = reinterpret_cast<SmK*>(smem_raw);

    const int ch   = blockIdx.x;
    const int b    = blockIdx.y + b0;
    const int tid  = threadIdx.x;
    const int lane = tid & 31;
    const int warp = tid >> 5;

    const float4* Sg4 = reinterpret_cast<const float4*>(support + (size_t)b * NS * D);

    // load 28 x 256 chunk (rows 25..27 zero)
    for (int idx = tid; idx < SROWS * CW4; idx += 256) {
        int row = idx / CW4;
        int k4  = idx - row * CW4;
        float4 v = make_float4(0.f, 0.f, 0.f, 0.f);
        if (row < NS)
            v = Sg4[row * D4 + ch * CW4 + k4];
        float* dst = &sm->Sc[row * CP + k4 * 4];
        dst[0] = v.x; dst[1] = v.y; dst[2] = v.z; dst[3] = v.w;
    }
    __syncthreads();

    float* outp = kp + ((size_t)b * NCHUNK + ch) * NS * NS;

    // 28 upper-triangle 4x4 block tiles over 8 warps
    for (int t = warp; t < 28; t += 8) {
        const int bi = t_bi[t] * 4;
        const int bj = t_bj[t] * 4;

        float acc[16];                  // acc[r*4+s]
        #pragma unroll
        for (int m = 0; m < 16; m++) acc[m] = 0.f;

        #pragma unroll
        for (int it = 0; it < 2; it++) {
            const int k = (lane + 32 * it) * 4;
            float4 a[4];
            #pragma unroll
            for (int r = 0; r < 4; r++)
                a[r] = *reinterpret_cast<const float4*>(&sm->Sc[(bi + r) * CP + k]);
            #pragma unroll
            for (int s = 0; s < 4; s++) {
                float4 bv = *reinterpret_cast<const float4*>(&sm->Sc[(bj + s) * CP + k]);
                #pragma unroll
                for (int r = 0; r < 4; r++)
                    acc[r * 4 + s] += a[r].x * bv.x + a[r].y * bv.y +
                                      a[r].z * bv.z + a[r].w * bv.w;
            }
        }

        reduce16(acc, lane);

        if ((lane & 1) == 0) {
            const int m = (lane >> 1) & 15;
            const int i = bi + (m >> 2);
            const int j = bj + (m & 3);
            if (i < NS && j < NS) {
                // duplicate writes (diagonal tiles) are bit-identical
                outp[i * NS + j] = acc[0];
                outp[j * NS + i] = acc[0];
            }
        }
    }
}

// ---------------------------------------------------------------------------
// Kernel 2: fused: reduce K partials + block-parallel Gauss-Jordan + W = S^T A
//           grid(Bslice), block 256   (R10 measured-good, FROZEN; + offset)
// ---------------------------------------------------------------------------
__global__ void __launch_bounds__(256, 5)
solve_w_kernel(const float* __restrict__ kp,
               const void* __restrict__ labels_raw,
               const float* __restrict__ support,
               float* __restrict__ wt_out,
               int b0)
{
    __shared__ float M[NS * AUGC];
    __shared__ float f[32];
    const int b    = blockIdx.x + b0;
    const int tid  = threadIdx.x;
    const int lane = tid & 31;
    const int warp = tid >> 5;

    // ---- reduce 4 chunk partials + lambda*I (all threads) ----------------
    const float* p0 = kp + (size_t)b * NCHUNK * NS * NS;
    for (int s = tid; s < NS * NS; s += 256) {
        int i = s / NS, j = s - i * NS;
        float v = p0[s] + p0[s + NS * NS] + p0[s + 2 * NS * NS] + p0[s + 3 * NS * NS];
        if (i == j) v += 1.0f;
        M[i * AUGC + j] = v;
    }
    for (int s = tid; s < NS * (AUGC - NS); s += 256) {
        int i = s / (AUGC - NS), j = s - i * (AUGC - NS);
        M[i * AUGC + NS + j] = 0.0f;
    }
    __syncthreads();

    if (warp == 0) {
        // label dtype detection (int64 vs int32) via first 25 entries
        const int* li = reinterpret_cast<const int*>(labels_raw);
        int hi = (lane < NS) ? li[2 * lane + 1] : 0;
        unsigned nz = __ballot_sync(0xffffffffu, hi != 0);
        bool is64 = (nz == 0);

        if (lane < NS) {
            long long lbl;
            if (is64)
                lbl = reinterpret_cast<const long long*>(labels_raw)[(size_t)b * NS + lane];
            else
                lbl = (long long)li[(size_t)b * NS + lane];
            M[lane * AUGC + NS + (int)lbl] = 1.0f;
        }
    }
    __syncthreads();

    // ---- block-parallel Gauss-Jordan (SPD, no pivoting, column-skip) -----
    for (int p = 0; p < NS; p++) {
        const float inv = 1.0f / M[p * AUGC + p];
        if (tid < NS) {
            if (tid != p) f[tid] = M[tid * AUGC + p];
        } else if (tid >= 32 && tid < 64) {
            const int j = tid - 32;
            if (j >= p && j < 30) M[p * AUGC + j] *= inv;
        }
        __syncthreads();
        #pragma unroll
        for (int it = 0; it < 4; it++) {
            const int s = tid + it * 256;
            const int i = s >> 5;
            const int j = s & 31;
            if (i < NS && i != p && j >= p && j < 30)
                M[i * AUGC + j] -= f[i] * M[p * AUGC + j];
        }
        __syncthreads();
    }
    // A[i][c] at M[i][25 + c]

    // ---- W^T[c][k] = sum_i S[i][k] A[i][c]  (S from L2) -------------------
    const float4* Sg4 = reinterpret_cast<const float4*>(support + (size_t)b * NS * D);
    float4 acc[NWAY];
    #pragma unroll
    for (int c = 0; c < NWAY; c++) acc[c] = make_float4(0.f, 0.f, 0.f, 0.f);

    #pragma unroll
    for (int i = 0; i < NS; i++) {
        float4 s = __ldg(&Sg4[i * D4 + tid]);
        #pragma unroll
        for (int c = 0; c < NWAY; c++) {
            float a = M[i * AUGC + NS + c];
            acc[c].x += s.x * a; acc[c].y += s.y * a;
            acc[c].z += s.z * a; acc[c].w += s.w * a;
        }
    }
    float4* Wt4 = reinterpret_cast<float4*>(wt_out + (size_t)b * NWAY * D);
    #pragma unroll
    for (int c = 0; c < NWAY; c++)
        Wt4[c * D4 + tid] = acc[c];
}

// ---------------------------------------------------------------------------
// Kernel 3: logits = scale * Q @ W
//           256 threads, 8 warps x 4 rows = 32 rows/CTA, grid(3, Bslice)
//           (R13 measured-good, FROZEN; + batch offset)
// ---------------------------------------------------------------------------
struct SmB { float Wt[NWAY * D]; };   // 20480 B

__global__ void __launch_bounds__(256, 5)
logits_kernel(const float* __restrict__ query,
              const float* __restrict__ wt_in,
              const float* __restrict__ scale,
              float* __restrict__ out,
              int NQ, int b0)
{
    extern __shared__ __align__(16) char smem_raw[];
    SmB* sm = reinterpret_cast<SmB*>(smem_raw);

    const int b    = blockIdx.y + b0;
    const int sub  = blockIdx.x;
    const int tid  = threadIdx.x;
    const int lane = tid & 31;
    const int warp = tid >> 5;

    // load W^T tile (1280 float4 / 256 threads = 5 each)
    {
        const float4* src = reinterpret_cast<const float4*>(wt_in + (size_t)b * NWAY * D);
        float4* dst = reinterpret_cast<float4*>(sm->Wt);
        #pragma unroll
        for (int i = 0; i < 5; i++)
            dst[tid + i * 256] = src[tid + i * 256];
    }
    __syncthreads();

    const int row0 = sub * ROWS_PER_CTA;
    const int rows = min(ROWS_PER_CTA, NQ - row0);
    if (rows <= 0) return;

    const int r0 = warp * 4;
    const int nr = min(4, rows - r0);
    if (nr <= 0) return;

    const float4* Q4 = reinterpret_cast<const float4*>(
        query + ((size_t)b * NQ + row0 + r0) * D);

    float acc[4][NWAY];
    #pragma unroll
    for (int r = 0; r < 4; r++)
        #pragma unroll
        for (int c = 0; c < NWAY; c++) acc[r][c] = 0.f;

    #pragma unroll
    for (int it = 0; it < 8; it++) {
        const int k4 = lane + 32 * it;
        float4 q[4];
        #pragma unroll
        for (int r = 0; r < 4; r++)
            q[r] = (r < nr) ? Q4[(size_t)r * D4 + k4]
                            : make_float4(0.f, 0.f, 0.f, 0.f);
        #pragma unroll
        for (int c = 0; c < NWAY; c++) {
            float4 w = *reinterpret_cast<const float4*>(&sm->Wt[c * D + k4 * 4]);
            #pragma unroll
            for (int r = 0; r < 4; r++)
                acc[r][c] += q[r].x * w.x + q[r].y * w.y +
                             q[r].z * w.z + q[r].w * w.w;
        }
    }

    const float scl = __ldg(scale);
    float* Ob = out + ((size_t)b * NQ + row0 + r0) * NWAY;
    #pragma unroll
    for (int r = 0; r < 4; r++)
        #pragma unroll
        for (int c = 0; c < NWAY; c++) {
            float v = acc[r][c];
            #pragma unroll
            for (int o = 16; o > 0; o >>= 1)
                v += __shfl_xor_sync(0xffffffffu, v, o);
            if (lane == 0 && r < nr)
                Ob[(size_t)r * NWAY + c] = scl * v;
        }
}

extern "C" void kernel_launch(void* const* d_in, const int* in_sizes, int n_in,
                              void* d_out, int out_size)
{
    const float* query   = (const float*)d_in[0];
    const float* support = (const float*)d_in[1];
    const void*  labels  = d_in[2];
    const float* scale   = (const float*)d_in[3];

    const int B  = in_sizes[1] / (NS * D);
    const int NQ = in_sizes[0] / (B * D);

    float *kp, *wt;
    cudaGetSymbolAddress((void**)&kp, g_Kp);
    cudaGetSymbolAddress((void**)&wt, g_Wt);

    cudaFuncSetAttribute(kpart_kernel,
                         cudaFuncAttributeMaxDynamicSharedMemorySize, (int)sizeof(SmK));
    cudaFuncSetAttribute(logits_kernel,
                         cudaFuncAttributeMaxDynamicSharedMemorySize, (int)sizeof(SmB));

    const int B0 = B / 2;
    const int B1 = B - B0;
    const bool fork = (B0 > 0 && B1 > 0);

    cudaStream_t s1 = 0;
    cudaEvent_t evA = 0, ev1 = 0;
    if (fork) {
        // Created per call (kernel_launch runs only for correctness + capture;
        // a few leaked handles, no device-memory allocation involved).
        cudaStreamCreateWithFlags(&s1, cudaStreamNonBlocking);
        cudaEventCreateWithFlags(&evA, cudaEventDisableTiming);
        cudaEventCreateWithFlags(&ev1, cudaEventDisableTiming);
    }

    const int chain0 = fork ? B0 : B;

    // ---- chain 0 (capture stream): kpart(H0) -> solve(H0) -> logits(H0) ---
    dim3 gk0(NCHUNK, chain0);
    kpart_kernel<<<gk0, 256, sizeof(SmK)>>>(support, kp, 0);
    if (fork) cudaEventRecord(evA, 0);   // chain 1 may start after kpart(H0)

    solve_w_kernel<<<chain0, 256>>>(kp, labels, support, wt, 0);

    dim3 gl0((NQ + ROWS_PER_CTA - 1) / ROWS_PER_CTA, chain0);
    logits_kernel<<<gl0, 256, sizeof(SmB)>>>(query, wt, scale, (float*)d_out, NQ, 0);

    // ---- chain 1 (forked stream), phase-shifted by one kpart stage --------
    if (fork) {
        cudaStreamWaitEvent(s1, evA, 0);

        dim3 gk1(NCHUNK, B1);
        kpart_kernel<<<gk1, 256, sizeof(SmK), s1>>>(support, kp, B0);

        solve_w_kernel<<<B1, 256, 0, s1>>>(kp, labels, support, wt, B0);

        dim3 gl1((NQ + ROWS_PER_CTA - 1) / ROWS_PER_CTA, B1);
        logits_kernel<<<gl1, 256, sizeof(SmB), s1>>>(query, wt, scale,
                                                     (float*)d_out, NQ, B0);

        cudaEventRecord(ev1, s1);
        cudaStreamWaitEvent(0, ev1, 0);   // rejoin capture stream
    }
}

// round 16
// speedup vs baseline: 1.2439x; 1.2439x over previous
#include <cuda_runtime.h>
#include <cstdint>
#include <cstddef>

#define D        1024
#define D4       256
#define NS       25
#define NWAY     5
#define NCHUNK   2
#define CW       512       // chunk width (floats)
#define CW4      128
#define CP       516       // chunk pitch (floats)
#define AUGC     32        // augmented matrix row stride
#define MAXB     1024
#define ROWS_PER_CTA 32    // logits: 8 warps x 4 rows

// global scratch
__device__ float g_Kp[MAXB * NCHUNK * NS * NS];  // partial K per chunk
__device__ float g_Wt[MAXB * NWAY * D];          // W^T class-major

// tile map: 15 upper-triangle pairs of 5 row-blocks (5 rows each)
__constant__ unsigned char c_bi[15] = {0,0,0,0,0,1,1,1,1,2,2,2,3,3,4};
__constant__ unsigned char c_bj[15] = {0,1,2,3,4,1,2,3,4,2,3,4,3,4,4};

// Multi-value butterfly over 32 slots: 31 shuffles; on exit lane l holds the
// warp-wide sum of a[l].
__device__ __forceinline__ void reduce32(float* a, int lane) {
    {
        const bool hi = (lane & 16) != 0;
        #pragma unroll
        for (int m = 0; m < 16; m++) {
            float mine  = hi ? a[m + 16] : a[m];
            float other = hi ? a[m]      : a[m + 16];
            a[m] = mine + __shfl_xor_sync(0xffffffffu, other, 16);
        }
    }
    {
        const bool hi = (lane & 8) != 0;
        #pragma unroll
        for (int m = 0; m < 8; m++) {
            float mine  = hi ? a[m + 8] : a[m];
            float other = hi ? a[m]     : a[m + 8];
            a[m] = mine + __shfl_xor_sync(0xffffffffu, other, 8);
        }
    }
    {
        const bool hi = (lane & 4) != 0;
        #pragma unroll
        for (int m = 0; m < 4; m++) {
            float mine  = hi ? a[m + 4] : a[m];
            float other = hi ? a[m]     : a[m + 4];
            a[m] = mine + __shfl_xor_sync(0xffffffffu, other, 4);
        }
    }
    {
        const bool hi = (lane & 2) != 0;
        #pragma unroll
        for (int m = 0; m < 2; m++) {
            float mine  = hi ? a[m + 2] : a[m];
            float other = hi ? a[m]     : a[m + 2];
            a[m] = mine + __shfl_xor_sync(0xffffffffu, other, 2);
        }
    }
    {
        const bool hi = (lane & 1) != 0;
        float mine  = hi ? a[1] : a[0];
        float other = hi ? a[0] : a[1];
        a[0] = mine + __shfl_xor_sync(0xffffffffu, other, 1);
    }
}

// ---------------------------------------------------------------------------
// Kernel 1: partial K = S_chunk S_chunk^T  -> g_Kp   grid(NCHUNK, B)
//           512-wide chunks, 5x5 tiles, reduce32
// ---------------------------------------------------------------------------
struct SmK { float Sc[NS * CP]; };                // 51600 B

__global__ void __launch_bounds__(256, 4)
kpart_kernel(const float* __restrict__ support, float* __restrict__ kp)
{
    extern __shared__ __align__(16) char smem_raw[];
    SmK* sm = reinterpret_cast<SmK*>(smem_raw);

    const int ch   = blockIdx.x;
    const int b    = blockIdx.y;
    const int tid  = threadIdx.x;
    const int lane = tid & 31;
    const int warp = tid >> 5;
    const int di   = lane / 5;        // output row within 5x5 tile (lane < 25)
    const int dj   = lane - di * 5;   // output col within tile

    const float4* Sg4 = reinterpret_cast<const float4*>(support + (size_t)b * NS * D);

    // load 25 x 512 chunk (3200 float4)
    for (int idx = tid; idx < NS * CW4; idx += 256) {
        int row  = idx >> 7;          // idx / 128
        int col4 = idx & 127;
        float4 v = Sg4[row * D4 + ch * CW4 + col4];
        float* dst = &sm->Sc[row * CP + col4 * 4];
        dst[0] = v.x; dst[1] = v.y; dst[2] = v.z; dst[3] = v.w;
    }
    __syncthreads();

    float* outp = kp + ((size_t)b * NCHUNK + ch) * NS * NS;

    // 15 upper-triangle 5x5 block tiles over 8 warps (2 rounds)
    for (int t = warp; t < 15; t += 8) {
        const int bi = c_bi[t] * 5;
        const int bj = c_bj[t] * 5;

        float acc[32];                // acc[r*5+s] in [0,25); rest zero-pad
        #pragma unroll
        for (int m = 0; m < 32; m++) acc[m] = 0.f;

        #pragma unroll
        for (int it = 0; it < 4; it++) {
            const int k = (lane + 32 * it) * 4;
            float4 a[5];
            #pragma unroll
            for (int r = 0; r < 5; r++)
                a[r] = *reinterpret_cast<const float4*>(&sm->Sc[(bi + r) * CP + k]);
            #pragma unroll
            for (int s = 0; s < 5; s++) {
                float4 bv = *reinterpret_cast<const float4*>(&sm->Sc[(bj + s) * CP + k]);
                #pragma unroll
                for (int r = 0; r < 5; r++)
                    acc[r * 5 + s] += a[r].x * bv.x + a[r].y * bv.y +
                                      a[r].z * bv.z + a[r].w * bv.w;
            }
        }

        reduce32(acc, lane);          // lane l now holds sum of acc[l]

        if (lane < 25) {
            const int i = bi + di;
            const int j = bj + dj;
            // duplicate writes (diagonal tiles) are bit-identical
            outp[i * NS + j] = acc[0];
            outp[j * NS + i] = acc[0];
        }
    }
}

// ---------------------------------------------------------------------------
// Kernel 2: fused: reduce K partials + block-parallel Gauss-Jordan + W = S^T A
//           grid(B), block 256   (R10 structure; 2 partials now)
// ---------------------------------------------------------------------------
__global__ void __launch_bounds__(256, 5)
solve_w_kernel(const float* __restrict__ kp,
               const void* __restrict__ labels_raw,
               const float* __restrict__ support,
               float* __restrict__ wt_out)
{
    __shared__ float M[NS * AUGC];
    __shared__ float f[32];
    const int b    = blockIdx.x;
    const int tid  = threadIdx.x;
    const int lane = tid & 31;
    const int warp = tid >> 5;

    // ---- reduce 2 chunk partials + lambda*I (all threads) ----------------
    const float* p0 = kp + (size_t)b * NCHUNK * NS * NS;
    for (int s = tid; s < NS * NS; s += 256) {
        int i = s / NS, j = s - i * NS;
        float v = p0[s] + p0[s + NS * NS];
        if (i == j) v += 1.0f;
        M[i * AUGC + j] = v;
    }
    for (int s = tid; s < NS * (AUGC - NS); s += 256) {
        int i = s / (AUGC - NS), j = s - i * (AUGC - NS);
        M[i * AUGC + NS + j] = 0.0f;
    }
    __syncthreads();

    if (warp == 0) {
        // label dtype detection (int64 vs int32) via first 25 entries
        const int* li = reinterpret_cast<const int*>(labels_raw);
        int hi = (lane < NS) ? li[2 * lane + 1] : 0;
        unsigned nz = __ballot_sync(0xffffffffu, hi != 0);
        bool is64 = (nz == 0);

        if (lane < NS) {
            long long lbl;
            if (is64)
                lbl = reinterpret_cast<const long long*>(labels_raw)[(size_t)b * NS + lane];
            else
                lbl = (long long)li[(size_t)b * NS + lane];
            M[lane * AUGC + NS + (int)lbl] = 1.0f;
        }
    }
    __syncthreads();

    // ---- block-parallel Gauss-Jordan (SPD, no pivoting, column-skip) -----
    for (int p = 0; p < NS; p++) {
        const float inv = 1.0f / M[p * AUGC + p];
        if (tid < NS) {
            if (tid != p) f[tid] = M[tid * AUGC + p];
        } else if (tid >= 32 && tid < 64) {
            const int j = tid - 32;
            if (j >= p && j < 30) M[p * AUGC + j] *= inv;
        }
        __syncthreads();
        #pragma unroll
        for (int it = 0; it < 4; it++) {
            const int s = tid + it * 256;
            const int i = s >> 5;
            const int j = s & 31;
            if (i < NS && i != p && j >= p && j < 30)
                M[i * AUGC + j] -= f[i] * M[p * AUGC + j];
        }
        __syncthreads();
    }
    // A[i][c] at M[i][25 + c]

    // ---- W^T[c][k] = sum_i S[i][k] A[i][c]  (S from L2) -------------------
    const float4* Sg4 = reinterpret_cast<const float4*>(support + (size_t)b * NS * D);
    float4 acc[NWAY];
    #pragma unroll
    for (int c = 0; c < NWAY; c++) acc[c] = make_float4(0.f, 0.f, 0.f, 0.f);

    #pragma unroll
    for (int i = 0; i < NS; i++) {
        float4 s = __ldg(&Sg4[i * D4 + tid]);
        #pragma unroll
        for (int c = 0; c < NWAY; c++) {
            float a = M[i * AUGC + NS + c];
            acc[c].x += s.x * a; acc[c].y += s.y * a;
            acc[c].z += s.z * a; acc[c].w += s.w * a;
        }
    }
    float4* Wt4 = reinterpret_cast<float4*>(wt_out + (size_t)b * NWAY * D);
    #pragma unroll
    for (int c = 0; c < NWAY; c++)
        Wt4[c * D4 + tid] = acc[c];
}

// ---------------------------------------------------------------------------
// Kernel 3: logits = scale * Q @ W
//           256 threads, 8 warps x 4 rows = 32 rows/CTA, grid(3, B)
//           (R13/R14 measured-good, FROZEN)
// ---------------------------------------------------------------------------
struct SmB { float Wt[NWAY * D]; };   // 20480 B

__global__ void __launch_bounds__(256, 5)
logits_kernel(const float* __restrict__ query,
              const float* __restrict__ wt_in,
              const float* __restrict__ scale,
              float* __restrict__ out,
              int NQ)
{
    extern __shared__ __align__(16) char smem_raw[];
    SmB* sm = reinterpret_cast<SmB*>(smem_raw);

    const int b    = blockIdx.y;
    const int sub  = blockIdx.x;
    const int tid  = threadIdx.x;
    const int lane = tid & 31;
    const int warp = tid >> 5;

    // load W^T tile (1280 float4 / 256 threads = 5 each)
    {
        const float4* src = reinterpret_cast<const float4*>(wt_in + (size_t)b * NWAY * D);
        float4* dst = reinterpret_cast<float4*>(sm->Wt);
        #pragma unroll
        for (int i = 0; i < 5; i++)
            dst[tid + i * 256] = src[tid + i * 256];
    }
    __syncthreads();

    const int row0 = sub * ROWS_PER_CTA;
    const int rows = min(ROWS_PER_CTA, NQ - row0);
    if (rows <= 0) return;

    const int r0 = warp * 4;
    const int nr = min(4, rows - r0);
    if (nr <= 0) return;

    const float4* Q4 = reinterpret_cast<const float4*>(
        query + ((size_t)b * NQ + row0 + r0) * D);

    float acc[4][NWAY];
    #pragma unroll
    for (int r = 0; r < 4; r++)
        #pragma unroll
        for (int c = 0; c < NWAY; c++) acc[r][c] = 0.f;

    #pragma unroll
    for (int it = 0; it < 8; it++) {
        const int k4 = lane + 32 * it;
        float4 q[4];
        #pragma unroll
        for (int r = 0; r < 4; r++)
            q[r] = (r < nr) ? Q4[(size_t)r * D4 + k4]
                            : make_float4(0.f, 0.f, 0.f, 0.f);
        #pragma unroll
        for (int c = 0; c < NWAY; c++) {
            float4 w = *reinterpret_cast<const float4*>(&sm->Wt[c * D + k4 * 4]);
            #pragma unroll
            for (int r = 0; r < 4; r++)
                acc[r][c] += q[r].x * w.x + q[r].y * w.y +
                             q[r].z * w.z + q[r].w * w.w;
        }
    }

    const float scl = __ldg(scale);
    float* Ob = out + ((size_t)b * NQ + row0 + r0) * NWAY;
    #pragma unroll
    for (int r = 0; r < 4; r++)
        #pragma unroll
        for (int c = 0; c < NWAY; c++) {
            float v = acc[r][c];
            #pragma unroll
            for (int o = 16; o > 0; o >>= 1)
                v += __shfl_xor_sync(0xffffffffu, v, o);
            if (lane == 0 && r < nr)
                Ob[(size_t)r * NWAY + c] = scl * v;
        }
}

extern "C" void kernel_launch(void* const* d_in, const int* in_sizes, int n_in,
                              void* d_out, int out_size)
{
    const float* query   = (const float*)d_in[0];
    const float* support = (const float*)d_in[1];
    const void*  labels  = d_in[2];
    const float* scale   = (const float*)d_in[3];

    const int B  = in_sizes[1] / (NS * D);
    const int NQ = in_sizes[0] / (B * D);

    float *kp, *wt;
    cudaGetSymbolAddress((void**)&kp, g_Kp);
    cudaGetSymbolAddress((void**)&wt, g_Wt);

    cudaFuncSetAttribute(kpart_kernel,
                         cudaFuncAttributeMaxDynamicSharedMemorySize, (int)sizeof(SmK));
    cudaFuncSetAttribute(logits_kernel,
                         cudaFuncAttributeMaxDynamicSharedMemorySize, (int)sizeof(SmB));

    dim3 g1(NCHUNK, B);
    kpart_kernel<<<g1, 256, sizeof(SmK)>>>(support, kp);

    solve_w_kernel<<<B, 256>>>(kp, labels, support, wt);

    dim3 g3((NQ + ROWS_PER_CTA - 1) / ROWS_PER_CTA, B);
    logits_kernel<<<g3, 256, sizeof(SmB)>>>(query, wt, scale, (float*)d_out, NQ);
}

// round 17
// speedup vs baseline: 1.4098x; 1.1334x over previous
#include <cuda_runtime.h>
#include <cstdint>
#include <cstddef>

#define D        1024
#define D4       256
#define NS       25
#define NWAY     5
#define NCHUNK   2
#define CW       512       // chunk width (floats)
#define CW4      128
#define CP       516       // chunk pitch (floats)
#define AUGC     32        // augmented matrix row stride
#define MAXB     1024
#define ROWS_PER_CTA 32    // logits: 8 warps x 4 rows

// global scratch
__device__ float g_Kp[MAXB * NCHUNK * NS * NS];  // partial K per chunk
__device__ float g_Wt[MAXB * NWAY * D];          // W^T class-major

// tile map: 15 upper-triangle pairs of 5 row-blocks (5 rows each)
__constant__ unsigned char c_bi[15] = {0,0,0,0,0,1,1,1,1,2,2,2,3,3,4};
__constant__ unsigned char c_bj[15] = {0,1,2,3,4,1,2,3,4,2,3,4,3,4,4};

__device__ __forceinline__ uint32_t smem_u32(const void* p) {
    return (uint32_t)__cvta_generic_to_shared(p);
}
__device__ __forceinline__ void cp_async16(uint32_t dst, const void* src) {
    asm volatile("cp.async.cg.shared.global [%0], [%1], 16;"
                 :: "r"(dst), "l"(src) : "memory");
}
__device__ __forceinline__ void cp_commit() {
    asm volatile("cp.async.commit_group;" ::: "memory");
}
template <int N>
__device__ __forceinline__ void cp_wait() {
    asm volatile("cp.async.wait_group %0;" :: "n"(N) : "memory");
}

// Multi-value butterfly over 32 slots: 31 shuffles; on exit lane l holds the
// warp-wide sum of a[l].
__device__ __forceinline__ void reduce32(float* a, int lane) {
    {
        const bool hi = (lane & 16) != 0;
        #pragma unroll
        for (int m = 0; m < 16; m++) {
            float mine  = hi ? a[m + 16] : a[m];
            float other = hi ? a[m]      : a[m + 16];
            a[m] = mine + __shfl_xor_sync(0xffffffffu, other, 16);
        }
    }
    {
        const bool hi = (lane & 8) != 0;
        #pragma unroll
        for (int m = 0; m < 8; m++) {
            float mine  = hi ? a[m + 8] : a[m];
            float other = hi ? a[m]     : a[m + 8];
            a[m] = mine + __shfl_xor_sync(0xffffffffu, other, 8);
        }
    }
    {
        const bool hi = (lane & 4) != 0;
        #pragma unroll
        for (int m = 0; m < 4; m++) {
            float mine  = hi ? a[m + 4] : a[m];
            float other = hi ? a[m]     : a[m + 4];
            a[m] = mine + __shfl_xor_sync(0xffffffffu, other, 4);
        }
    }
    {
        const bool hi = (lane & 2) != 0;
        #pragma unroll
        for (int m = 0; m < 2; m++) {
            float mine  = hi ? a[m + 2] : a[m];
            float other = hi ? a[m]     : a[m + 2];
            a[m] = mine + __shfl_xor_sync(0xffffffffu, other, 2);
        }
    }
    {
        const bool hi = (lane & 1) != 0;
        float mine  = hi ? a[1] : a[0];
        float other = hi ? a[0] : a[1];
        a[0] = mine + __shfl_xor_sync(0xffffffffu, other, 1);
    }
}

// ---------------------------------------------------------------------------
// Kernel 1: partial K = S_chunk S_chunk^T  -> g_Kp   grid(NCHUNK, B)
//           cp.async half-buffered: compute on half1 overlaps half2 DMA
// ---------------------------------------------------------------------------
struct SmK { float Sc[NS * CP]; };                // 51600 B

__global__ void __launch_bounds__(256, 4)
kpart_kernel(const float* __restrict__ support, float* __restrict__ kp)
{
    extern __shared__ __align__(16) char smem_raw[];
    SmK* sm = reinterpret_cast<SmK*>(smem_raw);

    const int ch   = blockIdx.x;
    const int b    = blockIdx.y;
    const int tid  = threadIdx.x;
    const int lane = tid & 31;
    const int warp = tid >> 5;
    const int di   = lane / 5;        // output row within 5x5 tile (lane < 25)
    const int dj   = lane - di * 5;   // output col within tile

    const float4* Sg4 = reinterpret_cast<const float4*>(support + (size_t)b * NS * D);

    // ---- issue async copy: half 0 (col4 0..63), then half 1 (64..127) -----
    #pragma unroll
    for (int h = 0; h < 2; h++) {
        for (int idx = tid; idx < NS * 64; idx += 256) {
            int row  = idx >> 6;
            int col4 = (idx & 63) + h * 64;
            cp_async16(smem_u32(&sm->Sc[row * CP + col4 * 4]),
                       &Sg4[row * D4 + ch * CW4 + col4]);
        }
        cp_commit();
    }

    cp_wait<1>();          // half 0 resident
    __syncthreads();

    float* outp = kp + ((size_t)b * NCHUNK + ch) * NS * NS;

    // ---- round 1 tile (t = warp, always < 15): overlap with half-1 DMA ----
    {
        const int bi = c_bi[warp] * 5;
        const int bj = c_bj[warp] * 5;

        float acc[32];
        #pragma unroll
        for (int m = 0; m < 32; m++) acc[m] = 0.f;

        // k-iters 0..1 use half 0 only (k4 = lane + 32*it < 64)
        #pragma unroll
        for (int it = 0; it < 2; it++) {
            const int k = (lane + 32 * it) * 4;
            float4 a[5];
            #pragma unroll
            for (int r = 0; r < 5; r++)
                a[r] = *reinterpret_cast<const float4*>(&sm->Sc[(bi + r) * CP + k]);
            #pragma unroll
            for (int s = 0; s < 5; s++) {
                float4 bv = *reinterpret_cast<const float4*>(&sm->Sc[(bj + s) * CP + k]);
                #pragma unroll
                for (int r = 0; r < 5; r++)
                    acc[r * 5 + s] += a[r].x * bv.x + a[r].y * bv.y +
                                      a[r].z * bv.z + a[r].w * bv.w;
            }
        }

        cp_wait<0>();      // half 1 resident
        __syncthreads();

        #pragma unroll
        for (int it = 2; it < 4; it++) {
            const int k = (lane + 32 * it) * 4;
            float4 a[5];
            #pragma unroll
            for (int r = 0; r < 5; r++)
                a[r] = *reinterpret_cast<const float4*>(&sm->Sc[(bi + r) * CP + k]);
            #pragma unroll
            for (int s = 0; s < 5; s++) {
                float4 bv = *reinterpret_cast<const float4*>(&sm->Sc[(bj + s) * CP + k]);
                #pragma unroll
                for (int r = 0; r < 5; r++)
                    acc[r * 5 + s] += a[r].x * bv.x + a[r].y * bv.y +
                                      a[r].z * bv.z + a[r].w * bv.w;
            }
        }

        reduce32(acc, lane);

        if (lane < 25) {
            const int i = bi + di;
            const int j = bj + dj;
            // duplicate writes (diagonal tiles) are bit-identical
            outp[i * NS + j] = acc[0];
            outp[j * NS + i] = acc[0];
        }
    }

    // ---- round 2 tile (t = warp + 8, valid for warps 0..6) ----------------
    {
        const int t = warp + 8;
        if (t < 15) {
            const int bi = c_bi[t] * 5;
            const int bj = c_bj[t] * 5;

            float acc[32];
            #pragma unroll
            for (int m = 0; m < 32; m++) acc[m] = 0.f;

            #pragma unroll
            for (int it = 0; it < 4; it++) {
                const int k = (lane + 32 * it) * 4;
                float4 a[5];
                #pragma unroll
                for (int r = 0; r < 5; r++)
                    a[r] = *reinterpret_cast<const float4*>(&sm->Sc[(bi + r) * CP + k]);
                #pragma unroll
                for (int s = 0; s < 5; s++) {
                    float4 bv = *reinterpret_cast<const float4*>(&sm->Sc[(bj + s) * CP + k]);
                    #pragma unroll
                    for (int r = 0; r < 5; r++)
                        acc[r * 5 + s] += a[r].x * bv.x + a[r].y * bv.y +
                                          a[r].z * bv.z + a[r].w * bv.w;
                }
            }

            reduce32(acc, lane);

            if (lane < 25) {
                const int i = bi + di;
                const int j = bj + dj;
                outp[i * NS + j] = acc[0];
                outp[j * NS + i] = acc[0];
            }
        }
    }
}

// ---------------------------------------------------------------------------
// Kernel 2: fused: reduce K partials + block-parallel Gauss-Jordan + W = S^T A
//           grid(B), block 256   (R16 measured-good, FROZEN)
// ---------------------------------------------------------------------------
__global__ void __launch_bounds__(256, 5)
solve_w_kernel(const float* __restrict__ kp,
               const void* __restrict__ labels_raw,
               const float* __restrict__ support,
               float* __restrict__ wt_out)
{
    __shared__ float M[NS * AUGC];
    __shared__ float f[32];
    const int b    = blockIdx.x;
    const int tid  = threadIdx.x;
    const int lane = tid & 31;
    const int warp = tid >> 5;

    // ---- reduce 2 chunk partials + lambda*I (all threads) ----------------
    const float* p0 = kp + (size_t)b * NCHUNK * NS * NS;
    for (int s = tid; s < NS * NS; s += 256) {
        int i = s / NS, j = s - i * NS;
        float v = p0[s] + p0[s + NS * NS];
        if (i == j) v += 1.0f;
        M[i * AUGC + j] = v;
    }
    for (int s = tid; s < NS * (AUGC - NS); s += 256) {
        int i = s / (AUGC - NS), j = s - i * (AUGC - NS);
        M[i * AUGC + NS + j] = 0.0f;
    }
    __syncthreads();

    if (warp == 0) {
        // label dtype detection (int64 vs int32) via first 25 entries
        const int* li = reinterpret_cast<const int*>(labels_raw);
        int hi = (lane < NS) ? li[2 * lane + 1] : 0;
        unsigned nz = __ballot_sync(0xffffffffu, hi != 0);
        bool is64 = (nz == 0);

        if (lane < NS) {
            long long lbl;
            if (is64)
                lbl = reinterpret_cast<const long long*>(labels_raw)[(size_t)b * NS + lane];
            else
                lbl = (long long)li[(size_t)b * NS + lane];
            M[lane * AUGC + NS + (int)lbl] = 1.0f;
        }
    }
    __syncthreads();

    // ---- block-parallel Gauss-Jordan (SPD, no pivoting, column-skip) -----
    for (int p = 0; p < NS; p++) {
        const float inv = 1.0f / M[p * AUGC + p];
        if (tid < NS) {
            if (tid != p) f[tid] = M[tid * AUGC + p];
        } else if (tid >= 32 && tid < 64) {
            const int j = tid - 32;
            if (j >= p && j < 30) M[p * AUGC + j] *= inv;
        }
        __syncthreads();
        #pragma unroll
        for (int it = 0; it < 4; it++) {
            const int s = tid + it * 256;
            const int i = s >> 5;
            const int j = s & 31;
            if (i < NS && i != p && j >= p && j < 30)
                M[i * AUGC + j] -= f[i] * M[p * AUGC + j];
        }
        __syncthreads();
    }
    // A[i][c] at M[i][25 + c]

    // ---- W^T[c][k] = sum_i S[i][k] A[i][c]  (S from L2) -------------------
    const float4* Sg4 = reinterpret_cast<const float4*>(support + (size_t)b * NS * D);
    float4 acc[NWAY];
    #pragma unroll
    for (int c = 0; c < NWAY; c++) acc[c] = make_float4(0.f, 0.f, 0.f, 0.f);

    #pragma unroll
    for (int i = 0; i < NS; i++) {
        float4 s = __ldg(&Sg4[i * D4 + tid]);
        #pragma unroll
        for (int c = 0; c < NWAY; c++) {
            float a = M[i * AUGC + NS + c];
            acc[c].x += s.x * a; acc[c].y += s.y * a;
            acc[c].z += s.z * a; acc[c].w += s.w * a;
        }
    }
    float4* Wt4 = reinterpret_cast<float4*>(wt_out + (size_t)b * NWAY * D);
    #pragma unroll
    for (int c = 0; c < NWAY; c++)
        Wt4[c * D4 + tid] = acc[c];
}

// ---------------------------------------------------------------------------
// Kernel 3: logits = scale * Q @ W
//           256 threads, 8 warps x 4 rows = 32 rows/CTA, grid(3, B)
//           (R13/R14 measured-good, FROZEN)
// ---------------------------------------------------------------------------
struct SmB { float Wt[NWAY * D]; };   // 20480 B

__global__ void __launch_bounds__(256, 5)
logits_kernel(const float* __restrict__ query,
              const float* __restrict__ wt_in,
              const float* __restrict__ scale,
              float* __restrict__ out,
              int NQ)
{
    extern __shared__ __align__(16) char smem_raw[];
    SmB* sm = reinterpret_cast<SmB*>(smem_raw);

    const int b    = blockIdx.y;
    const int sub  = blockIdx.x;
    const int tid  = threadIdx.x;
    const int lane = tid & 31;
    const int warp = tid >> 5;

    // load W^T tile (1280 float4 / 256 threads = 5 each)
    {
        const float4* src = reinterpret_cast<const float4*>(wt_in + (size_t)b * NWAY * D);
        float4* dst = reinterpret_cast<float4*>(sm->Wt);
        #pragma unroll
        for (int i = 0; i < 5; i++)
            dst[tid + i * 256] = src[tid + i * 256];
    }
    __syncthreads();

    const int row0 = sub * ROWS_PER_CTA;
    const int rows = min(ROWS_PER_CTA, NQ - row0);
    if (rows <= 0) return;

    const int r0 = warp * 4;
    const int nr = min(4, rows - r0);
    if (nr <= 0) return;

    const float4* Q4 = reinterpret_cast<const float4*>(
        query + ((size_t)b * NQ + row0 + r0) * D);

    float acc[4][NWAY];
    #pragma unroll
    for (int r = 0; r < 4; r++)
        #pragma unroll
        for (int c = 0; c < NWAY; c++) acc[r][c] = 0.f;

    #pragma unroll
    for (int it = 0; it < 8; it++) {
        const int k4 = lane + 32 * it;
        float4 q[4];
        #pragma unroll
        for (int r = 0; r < 4; r++)
            q[r] = (r < nr) ? Q4[(size_t)r * D4 + k4]
                            : make_float4(0.f, 0.f, 0.f, 0.f);
        #pragma unroll
        for (int c = 0; c < NWAY; c++) {
            float4 w = *reinterpret_cast<const float4*>(&sm->Wt[c * D + k4 * 4]);
            #pragma unroll
            for (int r = 0; r < 4; r++)
                acc[r][c] += q[r].x * w.x + q[r].y * w.y +
                             q[r].z * w.z + q[r].w * w.w;
        }
    }

    const float scl = __ldg(scale);
    float* Ob = out + ((size_t)b * NQ + row0 + r0) * NWAY;
    #pragma unroll
    for (int r = 0; r < 4; r++)
        #pragma unroll
        for (int c = 0; c < NWAY; c++) {
            float v = acc[r][c];
            #pragma unroll
            for (int o = 16; o > 0; o >>= 1)
                v += __shfl_xor_sync(0xffffffffu, v, o);
            if (lane == 0 && r < nr)
                Ob[(size_t)r * NWAY + c] = scl * v;
        }
}

extern "C" void kernel_launch(void* const* d_in, const int* in_sizes, int n_in,
                              void* d_out, int out_size)
{
    const float* query   = (const float*)d_in[0];
    const float* support = (const float*)d_in[1];
    const void*  labels  = d_in[2];
    const float* scale   = (const float*)d_in[3];

    const int B  = in_sizes[1] / (NS * D);
    const int NQ = in_sizes[0] / (B * D);

    float *kp, *wt;
    cudaGetSymbolAddress((void**)&kp, g_Kp);
    cudaGetSymbolAddress((void**)&wt, g_Wt);

    cudaFuncSetAttribute(kpart_kernel,
                         cudaFuncAttributeMaxDynamicSharedMemorySize, (int)sizeof(SmK));
    cudaFuncSetAttribute(logits_kernel,
                         cudaFuncAttributeMaxDynamicSharedMemorySize, (int)sizeof(SmB));

    dim3 g1(NCHUNK, B);
    kpart_kernel<<<g1, 256, sizeof(SmK)>>>(support, kp);

    solve_w_kernel<<<B, 256>>>(kp, labels, support, wt);

    dim3 g3((NQ + ROWS_PER_CTA - 1) / ROWS_PER_CTA, B);
    logits_kernel<<<g3, 256, sizeof(SmB)>>>(query, wt, scale, (float*)d_out, NQ);
}